// round 1
// baseline (speedup 1.0000x reference)
#include <cuda_runtime.h>
#include <math.h>

// Problem constants
#define LL 2048
#define BB 32
#define HH 1024
#define MM (LL*BB)   // 65536 rows, row m = l*BB + b

// Scratch (device globals: no runtime allocation allowed)
__device__ float g_pst[BB*HH];     // state @ W2^T + w2_b + w1_b   [B, H]
__device__ float g_score[MM];      // attention scores, layout [l*B + b]

// ---------------------------------------------------------------------------
// Kernel 1: pst[b,n] = sum_h state[b,h]*w2[n,h] + w2_b[n] + w1_b[n]
// One warp per (b,n) dot product, coalesced 128B reads, shfl reduction.
// ---------------------------------------------------------------------------
__global__ void pst_kernel(const float* __restrict__ state,
                           const float* __restrict__ w2,
                           const float* __restrict__ w1_b,
                           const float* __restrict__ w2_b) {
    int warp = (blockIdx.x * blockDim.x + threadIdx.x) >> 5;
    int lane = threadIdx.x & 31;
    if (warp >= BB * HH) return;
    int b = warp >> 10;        // / HH
    int n = warp & (HH - 1);
    const float* s = state + b * HH;
    const float* w = w2 + (size_t)n * HH;
    float acc = 0.f;
    #pragma unroll 4
    for (int h = lane; h < HH; h += 32) acc += s[h] * w[h];
    #pragma unroll
    for (int o = 16; o > 0; o >>= 1) acc += __shfl_xor_sync(0xffffffffu, acc, o);
    if (lane == 0) g_pst[b * HH + n] = acc + w1_b[n] + w2_b[n];
}

// ---------------------------------------------------------------------------
// Kernel 2: fused GEMM + tanh + v-dot.
// Each block owns 128 rows (m0..m0+127) and loops over all 8 N-tiles of 128.
// 128x128x8 shared tiles, 256 threads, 8x8 per-thread register block.
// score[m] = sum_n v[n] * tanh(enc[m]·w1[n] + pst[b,n])   (v_b cancels in softmax)
// ---------------------------------------------------------------------------
__global__ __launch_bounds__(256, 2)
void gemm_score_kernel(const float* __restrict__ A,   // enc [M, H]
                       const float* __restrict__ W,   // w1  [H, H] (row = out n, K-major)
                       const float* __restrict__ v) { // v_w [H]
    __shared__ float As[8][128];
    __shared__ float Bs[8][128];
    __shared__ float red[128][17];   // per-row partial score, per tx column (+pad)

    int tid = threadIdx.x;
    int tx = tid & 15;
    int ty = tid >> 4;
    int m0 = blockIdx.x * 128;
    int lr = tid >> 1;            // load row 0..127
    int lk = (tid & 1) * 4;       // k sub-offset 0 or 4

    const float* Arow = A + (size_t)(m0 + lr) * HH + lk;

    // zero this thread's reduction slots
    #pragma unroll
    for (int i = 0; i < 8; i++) red[ty * 8 + i][tx] = 0.f;

    for (int nt = 0; nt < 8; ++nt) {
        int n0 = nt * 128;
        const float* Wrow = W + (size_t)(n0 + lr) * HH + lk;

        float acc[8][8];
        #pragma unroll
        for (int i = 0; i < 8; i++)
            #pragma unroll
            for (int j = 0; j < 8; j++) acc[i][j] = 0.f;

        float4 a4 = *(const float4*)(Arow);
        float4 b4 = *(const float4*)(Wrow);

        for (int kt = 0; kt < HH; kt += 8) {
            __syncthreads();   // previous tile fully consumed
            As[lk + 0][lr] = a4.x; As[lk + 1][lr] = a4.y;
            As[lk + 2][lr] = a4.z; As[lk + 3][lr] = a4.w;
            Bs[lk + 0][lr] = b4.x; Bs[lk + 1][lr] = b4.y;
            Bs[lk + 2][lr] = b4.z; Bs[lk + 3][lr] = b4.w;
            __syncthreads();

            if (kt + 8 < HH) {   // prefetch next tile while computing
                a4 = *(const float4*)(Arow + kt + 8);
                b4 = *(const float4*)(Wrow + kt + 8);
            }

            #pragma unroll
            for (int k = 0; k < 8; ++k) {
                float4 x0 = *(const float4*)&As[k][ty * 8];
                float4 x1 = *(const float4*)&As[k][ty * 8 + 4];
                float4 y0 = *(const float4*)&Bs[k][tx * 8];
                float4 y1 = *(const float4*)&Bs[k][tx * 8 + 4];
                float ar[8] = {x0.x, x0.y, x0.z, x0.w, x1.x, x1.y, x1.z, x1.w};
                float br[8] = {y0.x, y0.y, y0.z, y0.w, y1.x, y1.y, y1.z, y1.w};
                #pragma unroll
                for (int i = 0; i < 8; i++)
                    #pragma unroll
                    for (int j = 0; j < 8; j++)
                        acc[i][j] += ar[i] * br[j];
            }
        }

        // epilogue: partial score for this N-tile
        #pragma unroll
        for (int i = 0; i < 8; i++) {
            int m = m0 + ty * 8 + i;
            int b = m & (BB - 1);
            const float* prow = g_pst + b * HH + n0;
            float p = 0.f;
            #pragma unroll
            for (int j = 0; j < 8; j++) {
                int nn = tx * 8 + j;
                float x = acc[i][j] + prow[nn];
                p += v[n0 + nn] * tanhf(x);
            }
            red[ty * 8 + i][tx] += p;
        }
    }

    __syncthreads();
    if (tid < 128) {
        float s = 0.f;
        #pragma unroll
        for (int j = 0; j < 16; j++) s += red[tid][j];
        g_score[m0 + tid] = s;
    }
}

// ---------------------------------------------------------------------------
// Kernel 3: softmax over L (axis 0) per batch column b.
// Writes att_weights directly into d_out at offset BB*HH, layout [l*B + b].
// ---------------------------------------------------------------------------
__global__ void softmax_kernel(float* __restrict__ out) {
    __shared__ float sdata[256];
    int b = blockIdx.x;
    int tid = threadIdx.x;

    float mx = -1e30f;
    for (int l = tid; l < LL; l += 256) mx = fmaxf(mx, g_score[l * BB + b]);
    sdata[tid] = mx;
    __syncthreads();
    for (int s = 128; s > 0; s >>= 1) {
        if (tid < s) sdata[tid] = fmaxf(sdata[tid], sdata[tid + s]);
        __syncthreads();
    }
    mx = sdata[0];
    __syncthreads();

    float sum = 0.f;
    for (int l = tid; l < LL; l += 256) sum += __expf(g_score[l * BB + b] - mx);
    sdata[tid] = sum;
    __syncthreads();
    for (int s = 128; s > 0; s >>= 1) {
        if (tid < s) sdata[tid] += sdata[tid + s];
        __syncthreads();
    }
    float inv = 1.f / sdata[0];

    float* w = out + BB * HH;
    for (int l = tid; l < LL; l += 256)
        w[l * BB + b] = __expf(g_score[l * BB + b] - mx) * inv;
}

// ---------------------------------------------------------------------------
// Kernel 4: context[b,h] = sum_l weights[l,b] * enc[l,b,h]
// grid (H/128, B), 128 threads; coalesced 512B reads per warp per l.
// ---------------------------------------------------------------------------
__global__ void context_kernel(const float* __restrict__ enc,
                               const float* __restrict__ wts,
                               float* __restrict__ ctx) {
    int b = blockIdx.y;
    int h = blockIdx.x * 128 + threadIdx.x;
    const float* e = enc + (size_t)b * HH + h;
    const float* wv = wts + b;
    float acc = 0.f;
    #pragma unroll 4
    for (int l = 0; l < LL; ++l)
        acc += wv[(size_t)l * BB] * e[(size_t)l * BB * HH];
    ctx[b * HH + h] = acc;
}

// ---------------------------------------------------------------------------
// Launch: output tuple layout = [context_vector (B*H) | att_weights (L*B)]
// ---------------------------------------------------------------------------
extern "C" void kernel_launch(void* const* d_in, const int* in_sizes, int n_in,
                              void* d_out, int out_size) {
    const float* enc = (const float*)d_in[0];   // [L,B,H]
    const float* lds = (const float*)d_in[1];   // [2,1,B,H] -> state = first B*H
    const float* w1w = (const float*)d_in[2];   // [H,H]
    const float* w1b = (const float*)d_in[3];   // [H]
    const float* w2w = (const float*)d_in[4];   // [H,H]
    const float* w2b = (const float*)d_in[5];   // [H]
    const float* vw  = (const float*)d_in[6];   // [1,H]
    // d_in[7] = v_b: cancels under softmax, unused

    float* out = (float*)d_out;

    pst_kernel<<<4096, 256>>>(lds, w2w, w1b, w2b);
    gemm_score_kernel<<<MM / 128, 256>>>(enc, w1w, vw);
    softmax_kernel<<<BB, 256>>>(out);
    context_kernel<<<dim3(HH / 128, BB), 128>>>(enc, out + BB * HH, out);
}

// round 3
// speedup vs baseline: 2.5301x; 2.5301x over previous
#include <cuda_runtime.h>
#include <cuda_bf16.h>
#include <cstdint>

#define LL 2048
#define BB 32
#define HH 1024
#define MM (LL*HH/HH*BB)   // 65536
#undef MM
#define MM (LL*BB)

// ---------------- device scratch (statics; no runtime allocation) ----------
__device__ uint2 g_ahi[MM*HH/4];   // enc hi, bf16 x4 per uint2, [m][k]
__device__ uint2 g_alo[MM*HH/4];   // enc lo
__device__ uint2 g_bhi[HH*HH/4];   // w1 hi, [n][k]
__device__ uint2 g_blo[HH*HH/4];   // w1 lo
__device__ float g_pstT[HH*BB];    // pstT[n*32+b] = state@W2^T + w2_b + w1_b
__device__ float g_score[MM];      // scores [l*B+b]
__device__ float g_cpart[32*BB*HH];

// ---------------- PTX helpers (base ISA only) ------------------------------
__device__ __forceinline__ uint32_t smem_u32(const void* p){
    uint32_t a;
    asm("{ .reg .u64 t; cvta.to.shared.u64 t, %1; cvt.u32.u64 %0, t; }" : "=r"(a) : "l"(p));
    return a;
}
__device__ __forceinline__ void ldsm4(uint32_t* r, uint32_t addr){
    asm volatile("ldmatrix.sync.aligned.m8n8.x4.shared.b16 {%0,%1,%2,%3}, [%4];"
        : "=r"(r[0]), "=r"(r[1]), "=r"(r[2]), "=r"(r[3]) : "r"(addr));
}
__device__ __forceinline__ void mma16816(float* c, const uint32_t* a, const uint32_t* b){
    asm volatile("mma.sync.aligned.m16n8k16.row.col.f32.bf16.bf16.f32 "
        "{%0,%1,%2,%3}, {%4,%5,%6,%7}, {%8,%9}, {%0,%1,%2,%3};"
        : "+f"(c[0]), "+f"(c[1]), "+f"(c[2]), "+f"(c[3])
        : "r"(a[0]), "r"(a[1]), "r"(a[2]), "r"(a[3]), "r"(b[0]), "r"(b[1]));
}
__device__ __forceinline__ void cp16(uint32_t dst, const void* src){
    asm volatile("cp.async.ca.shared.global [%0], [%1], 16;" :: "r"(dst), "l"(src));
}
__device__ __forceinline__ void cp_commit(){ asm volatile("cp.async.commit_group;" ::: "memory"); }
__device__ __forceinline__ void cp_wait1(){ asm volatile("cp.async.wait_group 1;" ::: "memory"); }
__device__ __forceinline__ void cp_wait0(){ asm volatile("cp.async.wait_group 0;" ::: "memory"); }

// ---------------- SMEM layout (bytes) --------------------------------------
// tile = 128 rows x 64 B data, padded to 80 B/row  -> 10240 B
// stage = [A_hi | A_lo | B_hi | B_lo]              -> 40960 B, 2 stages
#define TILE_SZ 10240
#define ST_SZ   40960
#define O_PST   81920                 // 128*33 floats = 16896 B
#define O_V     98816                 // 512 B
#define O_RED   99328                 // 128*17 floats = 8704 B
#define SMEM_BYTES 108032

// ---------------------------------------------------------------------------
// fp32 -> bf16 hi/lo split (writes packed 4 x bf16 per uint2)
// which: 0 -> enc (g_ahi/g_alo), 1 -> w1 (g_bhi/g_blo)
// ---------------------------------------------------------------------------
__global__ void conv_split(const float* __restrict__ src, int which, int n4){
    uint2* hi = which ? g_bhi : g_ahi;
    uint2* lo = which ? g_blo : g_alo;
    int i = blockIdx.x * blockDim.x + threadIdx.x;
    int stride = gridDim.x * blockDim.x;
    for (; i < n4; i += stride){
        float4 x = ((const float4*)src)[i];
        __nv_bfloat16 h0 = __float2bfloat16(x.x);
        __nv_bfloat16 h1 = __float2bfloat16(x.y);
        __nv_bfloat16 h2 = __float2bfloat16(x.z);
        __nv_bfloat16 h3 = __float2bfloat16(x.w);
        __nv_bfloat16 l0 = __float2bfloat16(x.x - __bfloat162float(h0));
        __nv_bfloat16 l1 = __float2bfloat16(x.y - __bfloat162float(h1));
        __nv_bfloat16 l2 = __float2bfloat16(x.z - __bfloat162float(h2));
        __nv_bfloat16 l3 = __float2bfloat16(x.w - __bfloat162float(h3));
        uint2 ph, pl;
        ph.x = ((uint32_t)__bfloat16_as_ushort(h1) << 16) | __bfloat16_as_ushort(h0);
        ph.y = ((uint32_t)__bfloat16_as_ushort(h3) << 16) | __bfloat16_as_ushort(h2);
        pl.x = ((uint32_t)__bfloat16_as_ushort(l1) << 16) | __bfloat16_as_ushort(l0);
        pl.y = ((uint32_t)__bfloat16_as_ushort(l3) << 16) | __bfloat16_as_ushort(l2);
        hi[i] = ph;
        lo[i] = pl;
    }
}

// ---------------------------------------------------------------------------
// pstT[n*32+b] = sum_h state[b,h]*w2[n,h] + w2_b[n] + w1_b[n]
// ---------------------------------------------------------------------------
__global__ void pstT_kernel(const float* __restrict__ state, const float* __restrict__ w2,
                            const float* __restrict__ w1b, const float* __restrict__ w2b){
    int gw = (blockIdx.x * blockDim.x + threadIdx.x) >> 5;
    int lane = threadIdx.x & 31;
    if (gw >= HH*8) return;
    int n = gw >> 3;
    int b0 = (gw & 7) * 4;
    const float* wr = w2 + (size_t)n * HH;
    float a0=0.f, a1=0.f, a2=0.f, a3=0.f;
    #pragma unroll 4
    for (int h = lane; h < HH; h += 32){
        float w = wr[h];
        a0 += w * state[(b0+0)*HH + h];
        a1 += w * state[(b0+1)*HH + h];
        a2 += w * state[(b0+2)*HH + h];
        a3 += w * state[(b0+3)*HH + h];
    }
    #pragma unroll
    for (int o = 16; o; o >>= 1){
        a0 += __shfl_xor_sync(~0u, a0, o);
        a1 += __shfl_xor_sync(~0u, a1, o);
        a2 += __shfl_xor_sync(~0u, a2, o);
        a3 += __shfl_xor_sync(~0u, a3, o);
    }
    if (lane == 0){
        float bias = w1b[n] + w2b[n];
        g_pstT[n*BB + b0+0] = a0 + bias;
        g_pstT[n*BB + b0+1] = a1 + bias;
        g_pstT[n*BB + b0+2] = a2 + bias;
        g_pstT[n*BB + b0+3] = a3 + bias;
    }
}

// ---------------------------------------------------------------------------
// cp.async one stage: 4 tiles of 128x32 bf16 (A_hi, A_lo, B_hi, B_lo)
// ---------------------------------------------------------------------------
__device__ __forceinline__ void cp_stage(uint32_t sb, int stage, int m0, int n0, int kt, int tid){
    uint32_t dbase = sb + stage*ST_SZ;
    int col = tid & 3;
    int r0  = tid >> 2;
    const char* bases[4] = { (const char*)g_ahi, (const char*)g_alo,
                             (const char*)g_bhi, (const char*)g_blo };
    #pragma unroll
    for (int t = 0; t < 4; ++t){
        int rowbase = (t < 2) ? m0 : n0;
        #pragma unroll
        for (int j = 0; j < 2; ++j){
            int row = r0 + j*64;
            const char* g = bases[t] + ((size_t)(rowbase + row)*HH + kt*32 + col*8)*2;
            uint32_t d = dbase + t*TILE_SZ + row*80 + col*16;
            cp16(d, g);
        }
    }
    cp_commit();
}

// ---------------------------------------------------------------------------
// fused GEMM (3x bf16 split) + tanh + v-dot
// CTA: 128 M-rows, loops 8 N-tiles of 128; 8 warps (2x4), warp tile 64x32
// ---------------------------------------------------------------------------
__global__ void __launch_bounds__(256, 1)
gemm_score(const float* __restrict__ v){
    extern __shared__ __align__(128) char smem[];
    uint32_t sb = smem_u32(smem);
    const int tid  = threadIdx.x;
    const int lane = tid & 31;
    const int wid  = tid >> 5;
    const int wm   = wid & 1;
    const int wn   = wid >> 1;
    const int m0   = blockIdx.x * 128;

    float* red   = (float*)(smem + O_RED);
    float* pst_s = (float*)(smem + O_PST);
    float* v_s   = (float*)(smem + O_V);

    for (int i = tid; i < 128*17; i += 256) red[i] = 0.f;

    // ldmatrix per-lane byte offsets within a tile
    const uint32_t aoff = (uint32_t)((wm*64 + (lane&7) + ((lane>>3)&1)*8) * 80 + ((lane>>4)*8)*2);
    const uint32_t boff = (uint32_t)((wn*32 + (lane&7) + (lane>>4)*8) * 80 + ((lane>>3)&1)*16);

    for (int nt = 0; nt < 8; ++nt){
        const int n0 = nt * 128;

        // load pst tile [128 n][32 b] (stride 33) and v tile
        {
            const float4* ps = (const float4*)(g_pstT + n0*BB);
            for (int i = tid; i < 1024; i += 256){
                float4 x = ps[i];
                int n = i >> 3, b4 = (i & 7) * 4;
                pst_s[n*33 + b4+0] = x.x; pst_s[n*33 + b4+1] = x.y;
                pst_s[n*33 + b4+2] = x.z; pst_s[n*33 + b4+3] = x.w;
            }
            if (tid < 128) v_s[tid] = v[n0 + tid];
        }

        float acc[4][4][4];
        #pragma unroll
        for (int a = 0; a < 4; a++)
            #pragma unroll
            for (int b = 0; b < 4; b++)
                #pragma unroll
                for (int c = 0; c < 4; c++) acc[a][b][c] = 0.f;

        cp_stage(sb, 0, m0, n0, 0, tid);

        for (int kt = 0; kt < 32; ++kt){
            if (kt < 31){ cp_stage(sb, (kt+1)&1, m0, n0, kt+1, tid); cp_wait1(); }
            else        { cp_wait0(); }
            __syncthreads();

            uint32_t sA_hi = sb + (kt&1)*ST_SZ;
            uint32_t sA_lo = sA_hi + TILE_SZ;
            uint32_t sB_hi = sA_hi + 2*TILE_SZ;
            uint32_t sB_lo = sA_hi + 3*TILE_SZ;

            #pragma unroll
            for (int ks = 0; ks < 2; ++ks){
                uint32_t ah[4][4], al[4][4], bh[4][2], bl[4][2];
                #pragma unroll
                for (int mf = 0; mf < 4; ++mf){
                    ldsm4(ah[mf], sA_hi + aoff + mf*(16*80) + ks*32);
                    ldsm4(al[mf], sA_lo + aoff + mf*(16*80) + ks*32);
                }
                #pragma unroll
                for (int np = 0; np < 2; ++np){
                    uint32_t q[4];
                    ldsm4(q, sB_hi + boff + np*(16*80) + ks*32);
                    bh[np*2+0][0]=q[0]; bh[np*2+0][1]=q[1];
                    bh[np*2+1][0]=q[2]; bh[np*2+1][1]=q[3];
                    ldsm4(q, sB_lo + boff + np*(16*80) + ks*32);
                    bl[np*2+0][0]=q[0]; bl[np*2+0][1]=q[1];
                    bl[np*2+1][0]=q[2]; bl[np*2+1][1]=q[3];
                }
                #pragma unroll
                for (int mf = 0; mf < 4; ++mf)
                    #pragma unroll
                    for (int nf = 0; nf < 4; ++nf){
                        mma16816(acc[mf][nf], ah[mf], bh[nf]);
                        mma16816(acc[mf][nf], ah[mf], bl[nf]);
                        mma16816(acc[mf][nf], al[mf], bh[nf]);
                    }
            }
            __syncthreads();
        }

        // epilogue: x = acc + pst; score partial += v * tanh(x)
        #pragma unroll
        for (int mf = 0; mf < 4; ++mf){
            #pragma unroll
            for (int hi = 0; hi < 2; ++hi){
                int row = wm*64 + mf*16 + (lane>>2) + hi*8;
                int b   = row & 31;
                float s = 0.f;
                #pragma unroll
                for (int nf = 0; nf < 4; ++nf){
                    #pragma unroll
                    for (int j = 0; j < 2; ++j){
                        int nl = wn*32 + nf*8 + (lane&3)*2 + j;
                        float x = acc[mf][nf][hi*2+j] + pst_s[nl*33 + b];
                        x = fminf(fmaxf(x, -15.f), 15.f);
                        float e = __expf(2.f*x);
                        float t = __fdividef(e - 1.f, e + 1.f);
                        s += v_s[nl] * t;
                    }
                }
                red[row*17 + wn*4 + (lane&3)] += s;
            }
        }
        __syncthreads();
    }

    if (tid < 128){
        const float* r = red + tid*17;
        float s = 0.f;
        #pragma unroll
        for (int j = 0; j < 16; ++j) s += r[j];
        g_score[m0 + tid] = s;
    }
}

// ---------------------------------------------------------------------------
// softmax over L per batch column b; weights -> out + B*H, layout [l*B+b]
// ---------------------------------------------------------------------------
__global__ void softmax_kernel(float* __restrict__ out){
    __shared__ float sdata[256];
    int b = blockIdx.x;
    int tid = threadIdx.x;

    float mx = -1e30f;
    for (int l = tid; l < LL; l += 256) mx = fmaxf(mx, g_score[l*BB + b]);
    sdata[tid] = mx; __syncthreads();
    for (int s = 128; s > 0; s >>= 1){ if (tid < s) sdata[tid] = fmaxf(sdata[tid], sdata[tid+s]); __syncthreads(); }
    mx = sdata[0]; __syncthreads();

    float sum = 0.f;
    for (int l = tid; l < LL; l += 256) sum += __expf(g_score[l*BB + b] - mx);
    sdata[tid] = sum; __syncthreads();
    for (int s = 128; s > 0; s >>= 1){ if (tid < s) sdata[tid] += sdata[tid+s]; __syncthreads(); }
    float inv = 1.f / sdata[0];

    float* w = out + BB*HH;
    for (int l = tid; l < LL; l += 256)
        w[l*BB + b] = __expf(g_score[l*BB + b] - mx) * inv;
}

// ---------------------------------------------------------------------------
// context: 32-way L-split partials, then reduce. float4 over H.
// ---------------------------------------------------------------------------
__global__ void ctx_part(const float* __restrict__ enc, const float* __restrict__ wts){
    int s = blockIdx.x;     // 0..31
    int b = blockIdx.y;     // 0..31
    int t = threadIdx.x;    // 0..255 -> float4 over H
    const float4* e = (const float4*)enc;
    float4 acc = make_float4(0.f, 0.f, 0.f, 0.f);
    int l0 = s * 64;
    #pragma unroll 4
    for (int l = 0; l < 64; ++l){
        float w = wts[(l0 + l)*BB + b];
        float4 x = e[((size_t)(l0 + l)*BB + b)*256 + t];
        acc.x += w*x.x; acc.y += w*x.y; acc.z += w*x.z; acc.w += w*x.w;
    }
    ((float4*)g_cpart)[((size_t)s*BB + b)*256 + t] = acc;
}
__global__ void ctx_reduce(float* __restrict__ out){
    int b = blockIdx.x;
    int t = threadIdx.x;
    float4 acc = make_float4(0.f, 0.f, 0.f, 0.f);
    #pragma unroll
    for (int s = 0; s < 32; ++s){
        float4 x = ((const float4*)g_cpart)[((size_t)s*BB + b)*256 + t];
        acc.x += x.x; acc.y += x.y; acc.z += x.z; acc.w += x.w;
    }
    ((float4*)out)[b*256 + t] = acc;
}

// ---------------------------------------------------------------------------
// launch: out = [context (B*H) | att_weights (L*B)]
// ---------------------------------------------------------------------------
extern "C" void kernel_launch(void* const* d_in, const int* in_sizes, int n_in,
                              void* d_out, int out_size) {
    const float* enc = (const float*)d_in[0];
    const float* lds = (const float*)d_in[1];   // state = first B*H floats
    const float* w1w = (const float*)d_in[2];
    const float* w1b = (const float*)d_in[3];
    const float* w2w = (const float*)d_in[4];
    const float* w2b = (const float*)d_in[5];
    const float* vw  = (const float*)d_in[6];
    // v_b cancels under softmax

    float* out = (float*)d_out;

    static bool attr_set = false;
    if (!attr_set){
        cudaFuncSetAttribute(gemm_score, cudaFuncAttributeMaxDynamicSharedMemorySize, SMEM_BYTES);
        attr_set = true;
    }

    conv_split<<<4096, 256>>>(enc, 0, MM*HH/4);
    conv_split<<<512, 256>>>(w1w, 1, HH*HH/4);
    pstT_kernel<<<1024, 256>>>(lds, w2w, w1b, w2b);
    gemm_score<<<MM/128, 256, SMEM_BYTES>>>(vw);
    softmax_kernel<<<BB, 256>>>(out);
    ctx_part<<<dim3(32, BB), 256>>>(enc, out + BB*HH);
    ctx_reduce<<<BB, 256>>>(out);
}